// round 17
// baseline (speedup 1.0000x reference)
#include <cuda_runtime.h>

#define FULL 0xffffffffu
#define BATCH 32768

// Fused VQC (math validated R7-R16): out_i = K_i * sum_T D_i[T] * sigma_T.
// R17: one-directional pipeline.
//   role 1 (warps 8-15): weights -> incremental delta phases (R15) -> warp
//     FWHT -> sD -> bar.arrive 1 -> retire. No input loads, no eval.
//   role 0 (warps 0-7): LDG + 8 sincos -> bar.sync 1 -> eval ALL 8 outputs
//     from registers + sD -> two coalesced STG.128.
// Single barrier, no sincos transport through smem, role-1 warps free their
// issue slots for role 0's eval.

__global__ __launch_bounds__(512) void vqc_fused(const float* __restrict__ inputs,
                                                 const float* __restrict__ weights,
                                                 float* __restrict__ out) {
    __shared__ float sD[8][256];

    const int tid  = threadIdx.x;
    const int lane = tid & 31;
    const int wid  = tid >> 5;
    const int eloc = tid & 255;
    const int e    = blockIdx.x * 256 + eloc;

    if (wid >= 8) {
        // ---- FWHT pipeline: warp (wid-8) builds table D_(wid-8) ----
        const int i  = wid - 8;
        const int sh = 6 - 2 * (i >> 1);
        const int A  = (((0xAA >> sh) << sh) >> (i & 1));
        const int msk[16]  = {0x01,0x03,0x06,0x0C,0x18,0x30,0x60,0xC0,
                              0x01,0x02,0x05,0x0A,0x14,0x28,0x50,0xA0};
        const int widx[16] = {7,6,5,4,3,2,1,0, 15,14,13,12,11,10,9,8};

        // tl[j] = (j in S_i) ? eps_j(lane)*theta_j : 0   (validated R15/R16)
        float tl[16];
#pragma unroll
        for (int j = 0; j < 16; j++) {
            float th = __ldg(&weights[widx[j]]);
            bool inS = (__popc(msk[j] & A) & 1);             // warp-uniform
            float v  = (__popc(msk[j] & lane) & 1) ? -th : th;
            tl[j] = inS ? v : 0.0f;
        }
        float d0 = 0.0f;
#pragma unroll
        for (int j = 0; j < 16; j++) d0 += tl[j];

        float U1 = tl[5] + tl[13];
        float U2 = tl[14];
        float U3 = tl[6];
        float U5 = tl[15];
        float U6 = tl[7];

        float F[8];
        F[0] = 0.0f;
        F[1] = U1 + U3 + U5;
        F[2] = U2 + U3 + U6;
        F[3] = U1 + U2 + U5 + U6;
        F[4] = U5 + U6;
        F[5] = U1 + U3 + U6;
        F[6] = U2 + U3 + U5;
        F[7] = U1 + U2;

        float C[8];
#pragma unroll
        for (int r = 0; r < 8; r++)
            C[r] = __cosf(fmaf(-2.0f, F[r], d0));

        // FWHT over w bits 5..7 (register butterflies)
#pragma unroll
        for (int sb = 1; sb < 8; sb <<= 1) {
            float t[8];
#pragma unroll
            for (int r = 0; r < 8; r++)
                t[r] = (r & sb) ? (C[r ^ sb] - C[r]) : (C[r] + C[r ^ sb]);
#pragma unroll
            for (int r = 0; r < 8; r++) C[r] = t[r];
        }
        // FWHT over w bits 0..4 (shuffle butterflies)
#pragma unroll
        for (int s = 1; s < 32; s <<= 1) {
            float sign = (lane & s) ? -1.0f : 1.0f;
#pragma unroll
            for (int r = 0; r < 8; r++) {
                float o = __shfl_xor_sync(FULL, C[r], s);
                C[r] = fmaf(sign, C[r], o);
            }
        }
#pragma unroll
        for (int r = 0; r < 8; r++)
            sD[i][r * 32 + lane] = C[r] * (1.0f / 256.0f);

        // sD published -> signal and retire
        asm volatile("bar.arrive 1, 512;" ::: "memory");
        return;
    }

    // ---- role 0: full element pipeline ----
    float sz0, cz0, sz1, cz1, sz2, cz2, sz3, cz3;
    float sz4, cz4, sz5, cz5, sz6, cz6, sz7, cz7;
    const float4 z0 = *reinterpret_cast<const float4*>(inputs + e * 8);
    const float4 z1 = *reinterpret_cast<const float4*>(inputs + e * 8 + 4);
    __sincosf(z0.x, &sz0, &cz0);  __sincosf(z0.y, &sz1, &cz1);
    __sincosf(z0.z, &sz2, &cz2);  __sincosf(z0.w, &sz3, &cz3);
    __sincosf(z1.x, &sz4, &cz4);  __sincosf(z1.y, &sz5, &cz5);
    __sincosf(z1.z, &sz6, &cz6);  __sincosf(z1.w, &sz7, &cz7);

    // sD-independent monomials / K products (pre-barrier)
    float s42 = sz4 * sz2, s40 = sz4 * sz0, s20 = sz2 * sz0, s420 = s42 * sz0;
    float m53 = sz5 * sz3, m51 = sz5 * sz1, m31 = sz3 * sz1, m531 = m53 * sz1;
    float s0C = sz5 * sz4;
    float Ke2 = cz0 * cz2, Ko2 = cz1 * cz3;
    float Ke3 = Ke2 * cz4, Ko3 = Ko2 * cz5;
    float K6  = Ke3 * cz6, K7  = Ko3 * cz7;

    asm volatile("bar.sync 1, 512;" ::: "memory");

    // ---- out0-3 (sparse; identical math to R9-R16) ----
    float o0 = cz0 * fmaf(sD[0][0x60], sz2 * sz1, sD[0][0x00]);

    float o1 = fmaf(sD[1][0xA0], s20, sD[1][0x00]);
    o1 = fmaf(sD[1][0x30], sz3 * sz2, o1);
    o1 = fmaf(sD[1][0x90], sz3 * sz0, o1);
    o1 *= cz1;

    float o2 = fmaf(sD[2][0x50], m31, sD[2][0x00]);
    o2 = fmaf(sD[2][0x18], sz4 * sz3, o2);
    o2 = fmaf(sD[2][0x48], sz4 * sz1, o2);
    o2 *= Ke2;

    float o3 = fmaf(sD[3][0x28], s42, sD[3][0x00]);
    o3 = fmaf(sD[3][0x0C], s0C, o3);
    o3 = fmaf(sD[3][0x24], sz5 * sz2, o3);
    o3 = fmaf(sD[3][0xA0], s20, o3);
    o3 = fmaf(sD[3][0x84], sz5 * sz0, o3);
    o3 = fmaf(sD[3][0xAC], s0C * s20, o3);
    o3 = fmaf(sD[3][0x88], s40, o3);
    o3 *= Ko2;

    // ---- out4 (identical math to R9-R16) ----
    float p4[4] = {1.0f, sz3, sz1, m31};
    const int b4[4] = {0, 16, 64, 80};
    float acc4 = 0.0f;
#pragma unroll
    for (int g = 0; g < 4; g++) {
        float4 a = *reinterpret_cast<const float4*>(&sD[4][b4[g]]);
        float4 b = *reinterpret_cast<const float4*>(&sD[4][b4[g] + 4]);
        float lo = fmaf(a.y, sz7, a.x) + sz6 * fmaf(a.w, sz7, a.z);
        float hi = fmaf(b.y, sz7, b.x) + sz6 * fmaf(b.w, sz7, b.z);
        acc4 = fmaf(p4[g], fmaf(sz5, hi, lo), acc4);
    }
    float o4 = Ke3 * acc4;

    // ---- out5-7 (identical math to R9-R16, from own registers) ----
    float p8[8] = {1.0f, sz4, sz2, s42, sz0, s40, s20, s420};
    float p6[8] = {1.0f, sz5, sz3, m53, sz1, m51, m31, m531};

    const int b5[8] = {0, 8, 32, 40, 128, 136, 160, 168};
    float acc5 = 0.0f;
#pragma unroll
    for (int g = 0; g < 8; g++) {
        float4 a = *reinterpret_cast<const float4*>(&sD[5][b5[g]]);
        float inner = fmaf(a.y, sz7, a.x) + sz6 * fmaf(a.w, sz7, a.z);
        acc5 = fmaf(p8[g], inner, acc5);
    }
    const int b6[8] = {0, 4, 16, 20, 64, 68, 80, 84};
    float acc6 = 0.0f;
#pragma unroll
    for (int g = 0; g < 8; g++) {
        float2 a = *reinterpret_cast<const float2*>(&sD[6][b6[g]]);
        acc6 = fmaf(p6[g], fmaf(a.y, sz7, a.x), acc6);
    }
    float acc7 = 0.0f;
#pragma unroll
    for (int g = 0; g < 8; g++) {
        float lo = sD[7][b5[g]];
        float hi = sD[7][b5[g] + 2];
        acc7 = fmaf(p8[g], fmaf(hi, sz6, lo), acc7);
    }
    float o5 = Ko3 * acc5;
    float o6 = K6  * acc6;
    float o7 = K7  * acc7;

    // fully coalesced 32B/thread stores
    *reinterpret_cast<float4*>(out + e * 8)     = make_float4(o0, o1, o2, o3);
    *reinterpret_cast<float4*>(out + e * 8 + 4) = make_float4(o4, o5, o6, o7);
}

extern "C" void kernel_launch(void* const* d_in, const int* in_sizes, int n_in,
                              void* d_out, int out_size) {
    const float* inputs  = (const float*)d_in[0];   // (32768, 8) float32
    const float* weights = (const float*)d_in[1];   // (2, 8)     float32
    float* out = (float*)d_out;                     // (32768, 8) float32

    // 128 blocks x 512 threads: warps 8-15 build sD then retire;
    // warps 0-7 sincos -> barrier -> eval all 8 outputs
    vqc_fused<<<BATCH / 256, 512>>>(inputs, weights, out);
}